// round 1
// baseline (speedup 1.0000x reference)
#include <cuda_runtime.h>
#include <math.h>

#define MAXN 500000
#define MAXV 50000

// ---- scratch (static __device__ arrays; allocation-free) ----
__device__ __align__(128) float g_pf2[(size_t)MAXN * 128];   // 256 MB
__device__ __align__(128) float g_vox[(size_t)MAXV * 128];   // segment-max of pf2
__device__ __align__(128) float g_voxf[(size_t)MAXV * 128];  // relu(vox@wv1+bv1)
__device__ __align__(128) float g_vox2[(size_t)MAXV * 256];  // segment-max of pf5

__device__ __forceinline__ void amax_pos(float* addr, float v) {
    // valid because all candidates are >= 0 and buffer is 0-initialized
    if (v > 0.f) atomicMax((int*)addr, __float_as_int(v));
}

// ---------------------------------------------------------------------------
// zero the two segment-max accumulators
// ---------------------------------------------------------------------------
__global__ void zero_k(int na, int nb) {
    int i = blockIdx.x * blockDim.x + threadIdx.x;
    int stride = gridDim.x * blockDim.x;
    for (int j = i; j < nb; j += stride) {
        if (j < na) g_vox[j] = 0.f;
        g_vox2[j] = 0.f;
    }
}

// ---------------------------------------------------------------------------
// Stage A: per-point MLPs + attention -> pf2, atomicMax into g_vox
// ---------------------------------------------------------------------------
#define SA_THREADS 128
#define SA_SMEM ((8832 + 2 * SA_THREADS * 65) * 4)

__global__ __launch_bounds__(SA_THREADS) void stage_a(
    const float* __restrict__ inp, const int* __restrict__ vidx, int n,
    const float* __restrict__ w1x, const float* __restrict__ b1x,
    const float* __restrict__ w2x, const float* __restrict__ b2x,
    const float* __restrict__ w1r, const float* __restrict__ b1r,
    const float* __restrict__ w2r, const float* __restrict__ b2r,
    const float* __restrict__ wax, const float* __restrict__ bax,
    const float* __restrict__ war, const float* __restrict__ bar)
{
    extern __shared__ float sm[];
    float* s_w  = sm;                        // 8832 weight floats
    float* s_t  = s_w + 8832;                // [128][65] hidden scratch
    float* s_cb = s_t + SA_THREADS * 65;     // [128][65] comb = [fx, fr]
    int t = threadIdx.x;

    {
        const float* srcs[12] = {w1x, b1x, w2x, b2x, w1r, b1r, w2r, b2r, wax, bax, war, bar};
        const int sizes[12]   = {192, 64, 2048, 32, 192, 64, 2048, 32, 2048, 32, 2048, 32};
        int off = 0;
        for (int a = 0; a < 12; a++) {
            for (int i = t; i < sizes[a]; i += SA_THREADS) s_w[off + i] = srcs[a][i];
            off += sizes[a];
        }
    }
    __syncthreads();

    const int ow1x = 0, ob1x = 192, ow2x = 256, ob2x = 2304;
    const int ow1r = 2336, ob1r = 2528, ow2r = 2592, ob2r = 4640;
    const int owax = 4672, obax = 6720, owar = 6752, obar = 8800;

    int p = blockIdx.x * SA_THREADS + t;
    if (p >= n) return;

    float* th = s_t + t * 65;
    float* cb = s_cb + t * 65;

    float i0 = inp[(size_t)p * 6 + 0], i1 = inp[(size_t)p * 6 + 1], i2 = inp[(size_t)p * 6 + 2];
    float i3 = inp[(size_t)p * 6 + 3], i4 = inp[(size_t)p * 6 + 4], i5 = inp[(size_t)p * 6 + 5];

    // xyz branch: 3 -> 64 -> 32
    for (int o = 0; o < 64; o++) {
        float a = s_w[ob1x + o] + i0 * s_w[ow1x + o] + i1 * s_w[ow1x + 64 + o] + i2 * s_w[ow1x + 128 + o];
        th[o] = fmaxf(a, 0.f);
    }
    for (int o = 0; o < 32; o++) {
        float a = s_w[ob2x + o];
#pragma unroll 8
        for (int j = 0; j < 64; j++) a += th[j] * s_w[ow2x + j * 32 + o];
        cb[o] = fmaxf(a, 0.f);
    }
    // rgb branch: 3 -> 64 -> 32
    for (int o = 0; o < 64; o++) {
        float a = s_w[ob1r + o] + i3 * s_w[ow1r + o] + i4 * s_w[ow1r + 64 + o] + i5 * s_w[ow1r + 128 + o];
        th[o] = fmaxf(a, 0.f);
    }
    for (int o = 0; o < 32; o++) {
        float a = s_w[ob2r + o];
#pragma unroll 8
        for (int j = 0; j < 64; j++) a += th[j] * s_w[ow2r + j * 32 + o];
        cb[32 + o] = fmaxf(a, 0.f);
    }

    // attention + pf2 + voxel max
    float* pf2row = g_pf2 + (size_t)p * 128;
    float* voxrow = g_vox + (size_t)vidx[p] * 128;
    for (int o = 0; o < 32; o++) {
        float ax = s_w[obax + o], ar = s_w[obar + o];
#pragma unroll 8
        for (int j = 0; j < 64; j++) {
            float cv = cb[j];
            ax += cv * s_w[owax + j * 32 + o];
            ar += cv * s_w[owar + j * 32 + o];
        }
        float sx = 1.f / (1.f + __expf(-ax));
        float sr = 1.f / (1.f + __expf(-ar));
        float fxv = cb[o], frv = cb[32 + o];
        float v0 = fxv, v1 = fxv * sx, v2 = frv, v3 = frv * sr;
        pf2row[o]      = v0; pf2row[32 + o] = v1;
        pf2row[64 + o] = v2; pf2row[96 + o] = v3;
        amax_pos(voxrow + o, v0);       amax_pos(voxrow + 32 + o, v1);
        amax_pos(voxrow + 64 + o, v2);  amax_pos(voxrow + 96 + o, v3);
    }
}

// ---------------------------------------------------------------------------
// Generic tiled GEMM: out[M,NC] = relu(A[M,K] @ W[K,NC] + bias)
// Block: 64 rows x NC cols, 256 threads, 8x(NC/32) register tiles.
// ---------------------------------------------------------------------------
template <int K, int NC>
__global__ __launch_bounds__(256) void gemm_relu(
    const float* __restrict__ A, const float* __restrict__ W,
    const float* __restrict__ bias, float* __restrict__ out, int M)
{
    extern __shared__ float sm[];
    float* a_s = sm;            // [K][68]  (A tile, k-major)
    float* b_s = sm + K * 68;   // [32][NC] (weight tile)
    const int TN = NC / 32;

    int t = threadIdx.x;
    int c = t & 31, r = t >> 5;
    int row0 = blockIdx.x * 64;

    // load A tile (k-major in smem)
    {
        int row = t >> 2, q = t & 3;
        int gr = min(row0 + row, M - 1);
        const float4* src = (const float4*)(A + (size_t)gr * K + q * (K / 4));
#pragma unroll
        for (int u = 0; u < K / 16; ++u) {
            float4 v = src[u];
            int k = q * (K / 4) + 4 * u;
            a_s[(k + 0) * 68 + row] = v.x;
            a_s[(k + 1) * 68 + row] = v.y;
            a_s[(k + 2) * 68 + row] = v.z;
            a_s[(k + 3) * 68 + row] = v.w;
        }
    }

    float acc[8][TN];
#pragma unroll
    for (int i = 0; i < 8; i++)
#pragma unroll
        for (int j = 0; j < TN; j++) acc[i][j] = 0.f;

    for (int kc = 0; kc < K / 32; ++kc) {
        {
            const float4* ws = (const float4*)(W + (size_t)(kc * 32 + (t >> 3)) * NC + (t & 7) * (NC / 8));
            float4* wd = (float4*)(b_s + (t >> 3) * NC + (t & 7) * (NC / 8));
#pragma unroll
            for (int q = 0; q < NC / 32; q++) wd[q] = ws[q];
        }
        __syncthreads();
#pragma unroll
        for (int k = 0; k < 32; k++) {
            const float* ar = a_s + (kc * 32 + k) * 68 + 8 * r;
            float4 a0 = *(const float4*)ar;
            float4 a1 = *(const float4*)(ar + 4);
            float av[8] = {a0.x, a0.y, a0.z, a0.w, a1.x, a1.y, a1.z, a1.w};
            const float* br = b_s + k * NC + 4 * c;
            float bv[TN];
            {
                float4 b0 = *(const float4*)br;
                bv[0] = b0.x; bv[1] = b0.y; bv[2] = b0.z; bv[3] = b0.w;
            }
            if (TN == 8) {
                float4 b1v = *(const float4*)(br + NC / 2);
                bv[4] = b1v.x; bv[5] = b1v.y; bv[6] = b1v.z; bv[7] = b1v.w;
            }
#pragma unroll
            for (int i = 0; i < 8; i++)
#pragma unroll
                for (int j = 0; j < TN; j++) acc[i][j] += av[i] * bv[j];
        }
        __syncthreads();
    }

    float bb[TN];
#pragma unroll
    for (int j = 0; j < TN; j++) {
        int col = (j < 4) ? 4 * c + j : NC / 2 + 4 * c + (j - 4);
        bb[j] = bias[col];
    }
#pragma unroll
    for (int i = 0; i < 8; i++) {
        int row = row0 + 8 * r + i;
        if (row < M) {
#pragma unroll
            for (int j = 0; j < TN; j++) {
                int col = (j < 4) ? 4 * c + j : NC / 2 + 4 * c + (j - 4);
                out[(size_t)row * NC + col] = fmaxf(acc[i][j] + bb[j], 0.f);
            }
        }
    }
}

// ---------------------------------------------------------------------------
// Stage C: fused  pf3 = [voxf[idx], pf2];  h = relu(pf3@w3+b3);
//          pf5 = relu(h@w4+b4);  atomicMax pf5 into g_vox2
// Block: 64 points, 256 threads, 8x8 register tiles, two chained GEMMs.
// ---------------------------------------------------------------------------
#define SC_SMEM ((256 * 68 + 32 * 256) * 4)

__global__ __launch_bounds__(256) void stage_c(
    const int* __restrict__ vidx, int n,
    const float* __restrict__ w3, const float* __restrict__ b3,
    const float* __restrict__ w4, const float* __restrict__ b4)
{
    extern __shared__ float sm[];
    float* a_s = sm;            // [256][68] pf3 tile (k-major), reused for h
    float* b_s = sm + 256 * 68; // [32][256] weight tile
    int t = threadIdx.x;
    int c = t & 31, r = t >> 5;
    int row0 = blockIdx.x * 64;

    // gather pf3 tile: warp r handles points 8r..8r+7, lane c covers 4 feats
#pragma unroll
    for (int i = 0; i < 8; i++) {
        int pt = row0 + 8 * r + i;
        int cp = min(pt, n - 1);
        int vr = vidx[cp];
        float4 v1 = *(const float4*)(g_voxf + (size_t)vr * 128 + 4 * c);
        float4 v2 = *(const float4*)(g_pf2 + (size_t)cp * 128 + 4 * c);
        int pr = 8 * r + i;
        a_s[(4 * c + 0) * 68 + pr] = v1.x;
        a_s[(4 * c + 1) * 68 + pr] = v1.y;
        a_s[(4 * c + 2) * 68 + pr] = v1.z;
        a_s[(4 * c + 3) * 68 + pr] = v1.w;
        a_s[(128 + 4 * c + 0) * 68 + pr] = v2.x;
        a_s[(128 + 4 * c + 1) * 68 + pr] = v2.y;
        a_s[(128 + 4 * c + 2) * 68 + pr] = v2.z;
        a_s[(128 + 4 * c + 3) * 68 + pr] = v2.w;
    }

    float acc[8][8];
#pragma unroll
    for (int i = 0; i < 8; i++)
#pragma unroll
        for (int j = 0; j < 8; j++) acc[i][j] = 0.f;

    // ---- GEMM1: pf3 @ w3 ----
    for (int kc = 0; kc < 8; ++kc) {
        {
            const float4* ws = (const float4*)(w3 + (size_t)(kc * 32 + (t >> 3)) * 256 + (t & 7) * 32);
            float4* wd = (float4*)(b_s + (t >> 3) * 256 + (t & 7) * 32);
#pragma unroll
            for (int q = 0; q < 8; q++) wd[q] = ws[q];
        }
        __syncthreads();
#pragma unroll
        for (int k = 0; k < 32; k++) {
            const float* ar = a_s + (kc * 32 + k) * 68 + 8 * r;
            float4 a0 = *(const float4*)ar;
            float4 a1 = *(const float4*)(ar + 4);
            float av[8] = {a0.x, a0.y, a0.z, a0.w, a1.x, a1.y, a1.z, a1.w};
            const float* br = b_s + k * 256 + 4 * c;
            float4 b0 = *(const float4*)br;
            float4 b1v = *(const float4*)(br + 128);
            float bv[8] = {b0.x, b0.y, b0.z, b0.w, b1v.x, b1v.y, b1v.z, b1v.w};
#pragma unroll
            for (int i = 0; i < 8; i++)
#pragma unroll
                for (int j = 0; j < 8; j++) acc[i][j] += av[i] * bv[j];
        }
        __syncthreads();
    }

    // write h = relu(acc + b3) into a_s (k-major), re-zero acc
#pragma unroll
    for (int j = 0; j < 8; j++) {
        int col = (j < 4) ? 4 * c + j : 128 + 4 * c + (j - 4);
        float bj = b3[col];
#pragma unroll
        for (int i = 0; i < 8; i++) {
            a_s[col * 68 + 8 * r + i] = fmaxf(acc[i][j] + bj, 0.f);
            acc[i][j] = 0.f;
        }
    }

    // ---- GEMM2: h @ w4 ----
    for (int kc = 0; kc < 8; ++kc) {
        {
            const float4* ws = (const float4*)(w4 + (size_t)(kc * 32 + (t >> 3)) * 256 + (t & 7) * 32);
            float4* wd = (float4*)(b_s + (t >> 3) * 256 + (t & 7) * 32);
#pragma unroll
            for (int q = 0; q < 8; q++) wd[q] = ws[q];
        }
        __syncthreads();
#pragma unroll
        for (int k = 0; k < 32; k++) {
            const float* ar = a_s + (kc * 32 + k) * 68 + 8 * r;
            float4 a0 = *(const float4*)ar;
            float4 a1 = *(const float4*)(ar + 4);
            float av[8] = {a0.x, a0.y, a0.z, a0.w, a1.x, a1.y, a1.z, a1.w};
            const float* br = b_s + k * 256 + 4 * c;
            float4 b0 = *(const float4*)br;
            float4 b1v = *(const float4*)(br + 128);
            float bv[8] = {b0.x, b0.y, b0.z, b0.w, b1v.x, b1v.y, b1v.z, b1v.w};
#pragma unroll
            for (int i = 0; i < 8; i++)
#pragma unroll
                for (int j = 0; j < 8; j++) acc[i][j] += av[i] * bv[j];
        }
        __syncthreads();
    }

    // epilogue: pf5 = relu(acc + b4) -> atomicMax into g_vox2
    float bb4[8];
#pragma unroll
    for (int j = 0; j < 8; j++) {
        int col = (j < 4) ? 4 * c + j : 128 + 4 * c + (j - 4);
        bb4[j] = b4[col];
    }
#pragma unroll
    for (int i = 0; i < 8; i++) {
        int pt = row0 + 8 * r + i;
        if (pt < n) {
            int vr = vidx[pt];
            float* dst = g_vox2 + (size_t)vr * 256;
#pragma unroll
            for (int j = 0; j < 8; j++) {
                int col = (j < 4) ? 4 * c + j : 128 + 4 * c + (j - 4);
                amax_pos(dst + col, fmaxf(acc[i][j] + bb4[j], 0.f));
            }
        }
    }
}

// ---------------------------------------------------------------------------
extern "C" void kernel_launch(void* const* d_in, const int* in_sizes, int n_in,
                              void* d_out, int out_size)
{
    const float* inp  = (const float*)d_in[0];
    const int*   vidx = (const int*)d_in[1];
    // num_vox may or may not be materialized as input 2; hedge on count
    int base = (n_in >= 23) ? 3 : 2;
    const float* w1x = (const float*)d_in[base + 0];
    const float* b1x = (const float*)d_in[base + 1];
    const float* w2x = (const float*)d_in[base + 2];
    const float* b2x = (const float*)d_in[base + 3];
    const float* w1r = (const float*)d_in[base + 4];
    const float* b1r = (const float*)d_in[base + 5];
    const float* w2r = (const float*)d_in[base + 6];
    const float* b2r = (const float*)d_in[base + 7];
    const float* wax = (const float*)d_in[base + 8];
    const float* bax = (const float*)d_in[base + 9];
    const float* war = (const float*)d_in[base + 10];
    const float* bar = (const float*)d_in[base + 11];
    const float* wv1 = (const float*)d_in[base + 12];
    const float* bv1 = (const float*)d_in[base + 13];
    const float* w3  = (const float*)d_in[base + 14];
    const float* b3  = (const float*)d_in[base + 15];
    const float* w4  = (const float*)d_in[base + 16];
    const float* b4  = (const float*)d_in[base + 17];
    const float* wv2 = (const float*)d_in[base + 18];
    const float* bv2 = (const float*)d_in[base + 19];

    int n = in_sizes[0] / 6;
    int V = out_size / 256;

    const int G1_SMEM = (128 * 68 + 32 * 128) * 4;  // 51200
    const int G2_SMEM = (256 * 68 + 32 * 256) * 4;  // 102400

    cudaFuncSetAttribute(stage_a, cudaFuncAttributeMaxDynamicSharedMemorySize, SA_SMEM);
    cudaFuncSetAttribute(stage_c, cudaFuncAttributeMaxDynamicSharedMemorySize, SC_SMEM);
    cudaFuncSetAttribute(gemm_relu<128, 128>, cudaFuncAttributeMaxDynamicSharedMemorySize, G1_SMEM);
    cudaFuncSetAttribute(gemm_relu<256, 256>, cudaFuncAttributeMaxDynamicSharedMemorySize, G2_SMEM);

    float *p_vox, *p_voxf, *p_vox2;
    cudaGetSymbolAddress((void**)&p_vox, g_vox);
    cudaGetSymbolAddress((void**)&p_voxf, g_voxf);
    cudaGetSymbolAddress((void**)&p_vox2, g_vox2);

    int zb = (V * 256 + 255) / 256;
    zero_k<<<zb, 256>>>(V * 128, V * 256);

    stage_a<<<(n + SA_THREADS - 1) / SA_THREADS, SA_THREADS, SA_SMEM>>>(
        inp, vidx, n, w1x, b1x, w2x, b2x, w1r, b1r, w2r, b2r, wax, bax, war, bar);

    gemm_relu<128, 128><<<(V + 63) / 64, 256, G1_SMEM>>>(p_vox, wv1, bv1, p_voxf, V);

    stage_c<<<(n + 63) / 64, 256, SC_SMEM>>>(vidx, n, w3, b3, w4, b4);

    gemm_relu<256, 256><<<(V + 63) / 64, 256, G2_SMEM>>>(p_vox2, wv2, bv2, (float*)d_out, V);
}

// round 3
// speedup vs baseline: 1.9090x; 1.9090x over previous
#include <cuda_runtime.h>
#include <cstdint>
#include <math.h>

#define MAXN 500000
#define MAXV 50000

// ---- scratch (static __device__ arrays; allocation-free) ----
__device__ __align__(128) float g_pf2[(size_t)MAXN * 128];
__device__ __align__(128) float g_vox[(size_t)MAXV * 128];
__device__ __align__(128) float g_voxf[(size_t)MAXV * 128];
__device__ __align__(128) float g_vox2[(size_t)MAXV * 256];
__device__ __align__(128) float g_w3t[65536];   // w3 pre-converted to tf32
__device__ __align__(128) float g_w4t[65536];   // w4 pre-converted to tf32

__device__ __forceinline__ void amax_pos(float* addr, float v) {
    if (v > 0.f) atomicMax((int*)addr, __float_as_int(v));
}

__device__ __forceinline__ uint32_t f2tf32(float f) {
    uint32_t r;
    asm("cvt.rna.tf32.f32 %0, %1;" : "=r"(r) : "f"(f));
    return r;
}

// ---------------------------------------------------------------------------
// zero accumulators
// ---------------------------------------------------------------------------
__global__ void zero_k(int na, int nb) {
    int i = blockIdx.x * blockDim.x + threadIdx.x;
    int stride = gridDim.x * blockDim.x;
    for (int j = i; j < nb; j += stride) {
        if (j < na) g_vox[j] = 0.f;
        g_vox2[j] = 0.f;
    }
}

// ---------------------------------------------------------------------------
// weight prep: elementwise tf32 round (keeps [k][n] row-major layout)
// ---------------------------------------------------------------------------
__global__ void prep_tf32(const float* __restrict__ w, float* __restrict__ dst) {
    int i = blockIdx.x * blockDim.x + threadIdx.x;
    if (i < 65536) dst[i] = __uint_as_float(f2tf32(w[i]));
}

// ---------------------------------------------------------------------------
// Stage A: per-point MLPs + attention -> pf2, atomicMax into g_vox
// ---------------------------------------------------------------------------
#define SA_THREADS 128
#define SA_SMEM ((8832 + 2 * SA_THREADS * 65) * 4)

__global__ __launch_bounds__(SA_THREADS) void stage_a(
    const float* __restrict__ inp, const int* __restrict__ vidx, int n,
    const float* __restrict__ w1x, const float* __restrict__ b1x,
    const float* __restrict__ w2x, const float* __restrict__ b2x,
    const float* __restrict__ w1r, const float* __restrict__ b1r,
    const float* __restrict__ w2r, const float* __restrict__ b2r,
    const float* __restrict__ wax, const float* __restrict__ bax,
    const float* __restrict__ war, const float* __restrict__ bar)
{
    extern __shared__ float sm[];
    float* s_w  = sm;
    float* s_t  = s_w + 8832;
    float* s_cb = s_t + SA_THREADS * 65;
    int t = threadIdx.x;
    {
        const float* srcs[12] = {w1x, b1x, w2x, b2x, w1r, b1r, w2r, b2r, wax, bax, war, bar};
        const int sizes[12]   = {192, 64, 2048, 32, 192, 64, 2048, 32, 2048, 32, 2048, 32};
        int off = 0;
        for (int a = 0; a < 12; a++) {
            for (int i = t; i < sizes[a]; i += SA_THREADS) s_w[off + i] = srcs[a][i];
            off += sizes[a];
        }
    }
    __syncthreads();
    const int ow1x = 0, ob1x = 192, ow2x = 256, ob2x = 2304;
    const int ow1r = 2336, ob1r = 2528, ow2r = 2592, ob2r = 4640;
    const int owax = 4672, obax = 6720, owar = 6752, obar = 8800;
    int p = blockIdx.x * SA_THREADS + t;
    if (p >= n) return;
    float* th = s_t + t * 65;
    float* cb = s_cb + t * 65;
    float i0 = inp[(size_t)p * 6 + 0], i1 = inp[(size_t)p * 6 + 1], i2 = inp[(size_t)p * 6 + 2];
    float i3 = inp[(size_t)p * 6 + 3], i4 = inp[(size_t)p * 6 + 4], i5 = inp[(size_t)p * 6 + 5];
    for (int o = 0; o < 64; o++) {
        float a = s_w[ob1x + o] + i0 * s_w[ow1x + o] + i1 * s_w[ow1x + 64 + o] + i2 * s_w[ow1x + 128 + o];
        th[o] = fmaxf(a, 0.f);
    }
    for (int o = 0; o < 32; o++) {
        float a = s_w[ob2x + o];
#pragma unroll 8
        for (int j = 0; j < 64; j++) a += th[j] * s_w[ow2x + j * 32 + o];
        cb[o] = fmaxf(a, 0.f);
    }
    for (int o = 0; o < 64; o++) {
        float a = s_w[ob1r + o] + i3 * s_w[ow1r + o] + i4 * s_w[ow1r + 64 + o] + i5 * s_w[ow1r + 128 + o];
        th[o] = fmaxf(a, 0.f);
    }
    for (int o = 0; o < 32; o++) {
        float a = s_w[ob2r + o];
#pragma unroll 8
        for (int j = 0; j < 64; j++) a += th[j] * s_w[ow2r + j * 32 + o];
        cb[32 + o] = fmaxf(a, 0.f);
    }
    float* pf2row = g_pf2 + (size_t)p * 128;
    float* voxrow = g_vox + (size_t)vidx[p] * 128;
    for (int o = 0; o < 32; o++) {
        float ax = s_w[obax + o], ar = s_w[obar + o];
#pragma unroll 8
        for (int j = 0; j < 64; j++) {
            float cv = cb[j];
            ax += cv * s_w[owax + j * 32 + o];
            ar += cv * s_w[owar + j * 32 + o];
        }
        float sx = 1.f / (1.f + __expf(-ax));
        float sr = 1.f / (1.f + __expf(-ar));
        float fxv = cb[o], frv = cb[32 + o];
        float v0 = fxv, v1 = fxv * sx, v2 = frv, v3 = frv * sr;
        pf2row[o]      = v0; pf2row[32 + o] = v1;
        pf2row[64 + o] = v2; pf2row[96 + o] = v3;
        amax_pos(voxrow + o, v0);       amax_pos(voxrow + 32 + o, v1);
        amax_pos(voxrow + 64 + o, v2);  amax_pos(voxrow + 96 + o, v3);
    }
}

// ---------------------------------------------------------------------------
// Generic tiled GEMM: out[M,NC] = relu(A[M,K] @ W[K,NC] + bias)
// ---------------------------------------------------------------------------
template <int K, int NC>
__global__ __launch_bounds__(256) void gemm_relu(
    const float* __restrict__ A, const float* __restrict__ W,
    const float* __restrict__ bias, float* __restrict__ out, int M)
{
    extern __shared__ float sm[];
    float* a_s = sm;
    float* b_s = sm + K * 68;
    const int TN = NC / 32;
    int t = threadIdx.x;
    int c = t & 31, r = t >> 5;
    int row0 = blockIdx.x * 64;
    {
        int row = t >> 2, q = t & 3;
        int gr = min(row0 + row, M - 1);
        const float4* src = (const float4*)(A + (size_t)gr * K + q * (K / 4));
#pragma unroll
        for (int u = 0; u < K / 16; ++u) {
            float4 v = src[u];
            int k = q * (K / 4) + 4 * u;
            a_s[(k + 0) * 68 + row] = v.x;
            a_s[(k + 1) * 68 + row] = v.y;
            a_s[(k + 2) * 68 + row] = v.z;
            a_s[(k + 3) * 68 + row] = v.w;
        }
    }
    float acc[8][TN];
#pragma unroll
    for (int i = 0; i < 8; i++)
#pragma unroll
        for (int j = 0; j < TN; j++) acc[i][j] = 0.f;
    for (int kc = 0; kc < K / 32; ++kc) {
        {
            const float4* ws = (const float4*)(W + (size_t)(kc * 32 + (t >> 3)) * NC + (t & 7) * (NC / 8));
            float4* wd = (float4*)(b_s + (t >> 3) * NC + (t & 7) * (NC / 8));
#pragma unroll
            for (int q = 0; q < NC / 32; q++) wd[q] = ws[q];
        }
        __syncthreads();
#pragma unroll
        for (int k = 0; k < 32; k++) {
            const float* ar = a_s + (kc * 32 + k) * 68 + 8 * r;
            float4 a0 = *(const float4*)ar;
            float4 a1 = *(const float4*)(ar + 4);
            float av[8] = {a0.x, a0.y, a0.z, a0.w, a1.x, a1.y, a1.z, a1.w};
            const float* br = b_s + k * NC + 4 * c;
            float bv[TN];
            {
                float4 b0 = *(const float4*)br;
                bv[0] = b0.x; bv[1] = b0.y; bv[2] = b0.z; bv[3] = b0.w;
            }
            if (TN == 8) {
                float4 b1v = *(const float4*)(br + NC / 2);
                bv[4] = b1v.x; bv[5] = b1v.y; bv[6] = b1v.z; bv[7] = b1v.w;
            }
#pragma unroll
            for (int i = 0; i < 8; i++)
#pragma unroll
                for (int j = 0; j < TN; j++) acc[i][j] += av[i] * bv[j];
        }
        __syncthreads();
    }
    float bb[TN];
#pragma unroll
    for (int j = 0; j < TN; j++) {
        int col = (j < 4) ? 4 * c + j : NC / 2 + 4 * c + (j - 4);
        bb[j] = bias[col];
    }
#pragma unroll
    for (int i = 0; i < 8; i++) {
        int row = row0 + 8 * r + i;
        if (row < M) {
#pragma unroll
            for (int j = 0; j < TN; j++) {
                int col = (j < 4) ? 4 * c + j : NC / 2 + 4 * c + (j - 4);
                out[(size_t)row * NC + col] = fmaxf(acc[i][j] + bb[j], 0.f);
            }
        }
    }
}

// ---------------------------------------------------------------------------
// Stage C via mma.sync tf32 (HMMA):
//   per CTA: 64 points, pf3 gathered into smem (tf32), two chained GEMMs
//   [64x256]@[256x256], epilogue1 writes h back to smem, epilogue2 atomicMax.
// Warp grid: 2(m) x 4(n); warp tile 32x64; m16n8k8 fragments.
// ---------------------------------------------------------------------------
#define SA_ST 260          // A row stride (floats): banks (4g+t4) conflict-free
#define SB_ST 264          // B row stride (floats): banks (8t4+g) conflict-free
#define SC_SMEM ((64 * SA_ST + 2 * 32 * SB_ST) * 4 + 256)

__global__ __launch_bounds__(256) void stage_c_mma(
    const int* __restrict__ vidx, int n,
    const float* __restrict__ b3, const float* __restrict__ b4)
{
    extern __shared__ float sm[];
    float* sA = sm;                          // [64][SA_ST]
    float* sB = sm + 64 * SA_ST;             // [2][32][SB_ST]
    int* svx = (int*)(sB + 2 * 32 * SB_ST);  // [64]

    int t = threadIdx.x;
    int lane = t & 31, wid = t >> 5;
    int g = lane >> 2, t4 = lane & 3;
    int wm = wid & 1, wn = wid >> 1;
    int row0 = blockIdx.x * 64;

    // ---- gather pf3 = [voxf[vidx[p]], pf2[p]] into sA as tf32 ----
    {
        int p = t >> 2, q = t & 3;
        int pt = row0 + p;
        int cp = min(pt, n - 1);
        int vr = vidx[cp];
        if (q == 0) svx[p] = vr;
        const float4* src = (q < 2)
            ? (const float4*)(g_voxf + (size_t)vr * 128 + q * 64)
            : (const float4*)(g_pf2 + (size_t)cp * 128 + (q - 2) * 64);
        float4* dst = (float4*)(sA + p * SA_ST + q * 64);
#pragma unroll
        for (int j = 0; j < 16; j++) {
            float4 v = src[j];
            v.x = __uint_as_float(f2tf32(v.x));
            v.y = __uint_as_float(f2tf32(v.y));
            v.z = __uint_as_float(f2tf32(v.z));
            v.w = __uint_as_float(f2tf32(v.w));
            dst[j] = v;
        }
    }

    float acc[2][8][4];
#pragma unroll
    for (int mt = 0; mt < 2; mt++)
#pragma unroll
        for (int nt = 0; nt < 8; nt++)
#pragma unroll
            for (int j = 0; j < 4; j++) acc[mt][nt][j] = 0.f;

    const float* wimg = (const float*)g_w3t;
    float4 pld[8];

    // preload w3 chunk 0 and stage it
    {
        const float4* ws = (const float4*)wimg;
#pragma unroll
        for (int i = 0; i < 8; i++) pld[i] = ws[t + i * 256];
#pragma unroll
        for (int i = 0; i < 8; i++) {
            int e = t + i * 256;
            int k = e >> 6, n4 = e & 63;
            *(float4*)(sB + k * SB_ST + n4 * 4) = pld[i];
        }
    }
    __syncthreads();

#pragma unroll 1
    for (int gg = 0; gg < 2; gg++) {
#pragma unroll 1
        for (int kc = 0; kc < 8; kc++) {
            if (kc < 7) {
                const float4* ws = (const float4*)(wimg + (kc + 1) * 32 * 256);
#pragma unroll
                for (int i = 0; i < 8; i++) pld[i] = ws[t + i * 256];
            }
            const float* bufB = sB + (kc & 1) * 32 * SB_ST;
#pragma unroll
            for (int k8 = 0; k8 < 4; k8++) {
                int k0 = kc * 32 + k8 * 8;
                uint32_t a[2][4];
#pragma unroll
                for (int mt = 0; mt < 2; mt++) {
                    const float* ap = sA + (wm * 32 + mt * 16 + g) * SA_ST + k0 + t4;
                    a[mt][0] = __float_as_uint(ap[0]);
                    a[mt][1] = __float_as_uint(ap[8 * SA_ST]);
                    a[mt][2] = __float_as_uint(ap[4]);
                    a[mt][3] = __float_as_uint(ap[8 * SA_ST + 4]);
                }
#pragma unroll
                for (int nt = 0; nt < 8; nt++) {
                    const float* bp = bufB + (k8 * 8 + t4) * SB_ST + wn * 64 + nt * 8 + g;
                    uint32_t b0 = __float_as_uint(bp[0]);
                    uint32_t b1 = __float_as_uint(bp[4 * SB_ST]);
#pragma unroll
                    for (int mt = 0; mt < 2; mt++) {
                        asm volatile(
                            "mma.sync.aligned.m16n8k8.row.col.f32.tf32.tf32.f32 "
                            "{%0,%1,%2,%3},{%4,%5,%6,%7},{%8,%9},{%0,%1,%2,%3};"
                            : "+f"(acc[mt][nt][0]), "+f"(acc[mt][nt][1]),
                              "+f"(acc[mt][nt][2]), "+f"(acc[mt][nt][3])
                            : "r"(a[mt][0]), "r"(a[mt][1]), "r"(a[mt][2]), "r"(a[mt][3]),
                              "r"(b0), "r"(b1));
                    }
                }
            }
            __syncthreads();
            if (kc < 7) {
                float* nb = sB + ((kc + 1) & 1) * 32 * SB_ST;
#pragma unroll
                for (int i = 0; i < 8; i++) {
                    int e = t + i * 256;
                    int k = e >> 6, n4 = e & 63;
                    *(float4*)(nb + k * SB_ST + n4 * 4) = pld[i];
                }
                __syncthreads();
            }
        }

        if (gg == 0) {
            // epilogue1: h = relu(acc + b3) -> sA (tf32), reset acc
#pragma unroll
            for (int nt = 0; nt < 8; nt++) {
                int c = wn * 64 + nt * 8 + 2 * t4;
                float bc0 = __ldg(b3 + c), bc1 = __ldg(b3 + c + 1);
#pragma unroll
                for (int mt = 0; mt < 2; mt++) {
                    int r = wm * 32 + mt * 16 + g;
                    float h0 = fmaxf(acc[mt][nt][0] + bc0, 0.f);
                    float h1 = fmaxf(acc[mt][nt][1] + bc1, 0.f);
                    float h2 = fmaxf(acc[mt][nt][2] + bc0, 0.f);
                    float h3 = fmaxf(acc[mt][nt][3] + bc1, 0.f);
                    *(float2*)(sA + r * SA_ST + c) =
                        make_float2(__uint_as_float(f2tf32(h0)), __uint_as_float(f2tf32(h1)));
                    *(float2*)(sA + (r + 8) * SA_ST + c) =
                        make_float2(__uint_as_float(f2tf32(h2)), __uint_as_float(f2tf32(h3)));
                    acc[mt][nt][0] = 0.f; acc[mt][nt][1] = 0.f;
                    acc[mt][nt][2] = 0.f; acc[mt][nt][3] = 0.f;
                }
            }
            // preload w4 chunk 0
            wimg = (const float*)g_w4t;
            {
                const float4* ws = (const float4*)wimg;
#pragma unroll
                for (int i = 0; i < 8; i++) pld[i] = ws[t + i * 256];
#pragma unroll
                for (int i = 0; i < 8; i++) {
                    int e = t + i * 256;
                    int k = e >> 6, n4 = e & 63;
                    *(float4*)(sB + k * SB_ST + n4 * 4) = pld[i];
                }
            }
            __syncthreads();
        }
    }

    // epilogue2: pf5 = relu(acc + b4) -> atomicMax scatter into g_vox2
#pragma unroll
    for (int mt = 0; mt < 2; mt++) {
        int lr = wm * 32 + mt * 16 + g;
        int pt0 = row0 + lr, pt1 = pt0 + 8;
        int vr0 = svx[lr], vr1 = svx[lr + 8];
        bool ok0 = pt0 < n, ok1 = pt1 < n;
        float* d0 = g_vox2 + (size_t)vr0 * 256;
        float* d1 = g_vox2 + (size_t)vr1 * 256;
#pragma unroll
        for (int nt = 0; nt < 8; nt++) {
            int c = wn * 64 + nt * 8 + 2 * t4;
            float bc0 = __ldg(b4 + c), bc1 = __ldg(b4 + c + 1);
            if (ok0) {
                amax_pos(d0 + c,     acc[mt][nt][0] + bc0);
                amax_pos(d0 + c + 1, acc[mt][nt][1] + bc1);
            }
            if (ok1) {
                amax_pos(d1 + c,     acc[mt][nt][2] + bc0);
                amax_pos(d1 + c + 1, acc[mt][nt][3] + bc1);
            }
        }
    }
}

// ---------------------------------------------------------------------------
extern "C" void kernel_launch(void* const* d_in, const int* in_sizes, int n_in,
                              void* d_out, int out_size)
{
    const float* inp  = (const float*)d_in[0];
    const int*   vidx = (const int*)d_in[1];
    int base = (n_in >= 23) ? 3 : 2;
    const float* w1x = (const float*)d_in[base + 0];
    const float* b1x = (const float*)d_in[base + 1];
    const float* w2x = (const float*)d_in[base + 2];
    const float* b2x = (const float*)d_in[base + 3];
    const float* w1r = (const float*)d_in[base + 4];
    const float* b1r = (const float*)d_in[base + 5];
    const float* w2r = (const float*)d_in[base + 6];
    const float* b2r = (const float*)d_in[base + 7];
    const float* wax = (const float*)d_in[base + 8];
    const float* bax = (const float*)d_in[base + 9];
    const float* war = (const float*)d_in[base + 10];
    const float* bar = (const float*)d_in[base + 11];
    const float* wv1 = (const float*)d_in[base + 12];
    const float* bv1 = (const float*)d_in[base + 13];
    const float* w3  = (const float*)d_in[base + 14];
    const float* b3  = (const float*)d_in[base + 15];
    const float* w4  = (const float*)d_in[base + 16];
    const float* b4  = (const float*)d_in[base + 17];
    const float* wv2 = (const float*)d_in[base + 18];
    const float* bv2 = (const float*)d_in[base + 19];

    int n = in_sizes[0] / 6;
    int V = out_size / 256;

    const int G1_SMEM = (128 * 68 + 32 * 128) * 4;
    const int G2_SMEM = (256 * 68 + 32 * 256) * 4;

    cudaFuncSetAttribute(stage_a, cudaFuncAttributeMaxDynamicSharedMemorySize, SA_SMEM);
    cudaFuncSetAttribute(stage_c_mma, cudaFuncAttributeMaxDynamicSharedMemorySize, SC_SMEM);
    cudaFuncSetAttribute(gemm_relu<128, 128>, cudaFuncAttributeMaxDynamicSharedMemorySize, G1_SMEM);
    cudaFuncSetAttribute(gemm_relu<256, 256>, cudaFuncAttributeMaxDynamicSharedMemorySize, G2_SMEM);

    float *p_vox, *p_voxf, *p_vox2, *p_w3t, *p_w4t;
    cudaGetSymbolAddress((void**)&p_vox, g_vox);
    cudaGetSymbolAddress((void**)&p_voxf, g_voxf);
    cudaGetSymbolAddress((void**)&p_vox2, g_vox2);
    cudaGetSymbolAddress((void**)&p_w3t, g_w3t);
    cudaGetSymbolAddress((void**)&p_w4t, g_w4t);

    int zb = (V * 256 + 255) / 256;
    zero_k<<<zb, 256>>>(V * 128, V * 256);
    prep_tf32<<<256, 256>>>(w3, p_w3t);
    prep_tf32<<<256, 256>>>(w4, p_w4t);

    stage_a<<<(n + SA_THREADS - 1) / SA_THREADS, SA_THREADS, SA_SMEM>>>(
        inp, vidx, n, w1x, b1x, w2x, b2x, w1r, b1r, w2r, b2r, wax, bax, war, bar);

    gemm_relu<128, 128><<<(V + 63) / 64, 256, G1_SMEM>>>(p_vox, wv1, bv1, p_voxf, V);

    stage_c_mma<<<(n + 63) / 64, 256, SC_SMEM>>>(vidx, n, b3, b4);

    gemm_relu<256, 256><<<(V + 63) / 64, 256, G2_SMEM>>>(p_vox2, wv2, bv2, (float*)d_out, V);
}

// round 4
// speedup vs baseline: 3.1700x; 1.6606x over previous
#include <cuda_runtime.h>
#include <cstdint>
#include <math.h>

#define MAXN 500000
#define MAXV 50000

// ---- scratch (static __device__ arrays; allocation-free) ----
__device__ __align__(128) float g_pf2[(size_t)MAXN * 128];
__device__ __align__(128) float g_vox[(size_t)MAXV * 128];
__device__ __align__(128) float g_voxf[(size_t)MAXV * 128];
__device__ __align__(128) float g_vox2[(size_t)MAXV * 256];
__device__ __align__(128) float g_w3t[65536];   // w3 pre-converted to tf32
__device__ __align__(128) float g_w4t[65536];   // w4 pre-converted to tf32

__device__ __forceinline__ void amax_pos(float* addr, float v) {
    if (v > 0.f) atomicMax((int*)addr, __float_as_int(v));
}

__device__ __forceinline__ uint32_t f2tf32(float f) {
    uint32_t r;
    asm("cvt.rna.tf32.f32 %0, %1;" : "=r"(r) : "f"(f));
    return r;
}
__device__ __forceinline__ float tf32f(float f) { return __uint_as_float(f2tf32(f)); }

// ---------------------------------------------------------------------------
// zero accumulators
// ---------------------------------------------------------------------------
__global__ void zero_k(int na, int nb) {
    int i = blockIdx.x * blockDim.x + threadIdx.x;
    int stride = gridDim.x * blockDim.x;
    for (int j = i; j < nb; j += stride) {
        if (j < na) g_vox[j] = 0.f;
        g_vox2[j] = 0.f;
    }
}

// ---------------------------------------------------------------------------
// weight prep: elementwise tf32 round (keeps [k][n] row-major layout)
// ---------------------------------------------------------------------------
__global__ void prep_tf32(const float* __restrict__ w, float* __restrict__ dst) {
    int i = blockIdx.x * blockDim.x + threadIdx.x;
    if (i < 65536) dst[i] = __uint_as_float(f2tf32(w[i]));
}

// ---------------------------------------------------------------------------
// shared GEMM micro-kernel: [16x64]@[64x32] per warp, m16n8k8 tf32
// A rows = wr..wr+15 in As (stride 68); B = Bt [64][40] (k-major)
// ---------------------------------------------------------------------------
__device__ __forceinline__ void gemm64x32(const float* __restrict__ As,
                                          const float* __restrict__ Bt,
                                          int wr, int g, int t4, float acc[4][4]) {
#pragma unroll
    for (int k8 = 0; k8 < 8; k8++) {
        const float* ap = As + (wr + g) * 68 + k8 * 8 + t4;
        uint32_t a0 = __float_as_uint(ap[0]);
        uint32_t a1 = __float_as_uint(ap[8 * 68]);
        uint32_t a2 = __float_as_uint(ap[4]);
        uint32_t a3 = __float_as_uint(ap[8 * 68 + 4]);
#pragma unroll
        for (int nt = 0; nt < 4; nt++) {
            const float* bp = Bt + (k8 * 8 + t4) * 40 + nt * 8 + g;
            uint32_t b0 = __float_as_uint(bp[0]);
            uint32_t b1 = __float_as_uint(bp[4 * 40]);
            asm volatile(
                "mma.sync.aligned.m16n8k8.row.col.f32.tf32.tf32.f32 "
                "{%0,%1,%2,%3},{%4,%5,%6,%7},{%8,%9},{%0,%1,%2,%3};"
                : "+f"(acc[nt][0]), "+f"(acc[nt][1]), "+f"(acc[nt][2]), "+f"(acc[nt][3])
                : "r"(a0), "r"(a1), "r"(a2), "r"(a3), "r"(b0), "r"(b1));
        }
    }
}

// ---------------------------------------------------------------------------
// Stage A via mma.sync tf32:
//   CTA = 128 points, 256 threads (8 warps, 16 rows each, warp-local tiles).
//   layer1 (K=3) elementwise -> th tile; 4 GEMMs [128x64]@[64x32];
//   epilogue: sigmoid gates, pf2 store, atomicMax into g_vox.
// smem floats: sW 512 | sB 4*2560 | sA 128*68 | sC 128*68 | svx 128
// ---------------------------------------------------------------------------
#define SAM_THREADS 256
#define SAM_SMEM (28288 * 4)

__global__ __launch_bounds__(SAM_THREADS) void stage_a_mma(
    const float* __restrict__ inp, const int* __restrict__ vidx, int n,
    const float* __restrict__ w1x, const float* __restrict__ b1x,
    const float* __restrict__ w2x, const float* __restrict__ b2x,
    const float* __restrict__ w1r, const float* __restrict__ b1r,
    const float* __restrict__ w2r, const float* __restrict__ b2r,
    const float* __restrict__ wax, const float* __restrict__ bax,
    const float* __restrict__ war, const float* __restrict__ bar)
{
    extern __shared__ float sm[];
    float* sW = sm;              // layer1 weights+bias (raw fp32)
    float* sB = sm + 512;        // 4 x [64][40] tf32 B tiles
    float* sA = sm + 10752;      // [128][68] hidden tile (tf32)
    float* sC = sm + 19456;      // [128][68] comb tile (tf32)
    int*   svx = (int*)(sm + 28160);

    int t = threadIdx.x;
    int lane = t & 31, w = t >> 5;
    int g = lane >> 2, t4 = lane & 3;
    int wr = 16 * w;
    int row0 = blockIdx.x * 128;

    // ---- stage weights ----
    for (int i = t; i < 192; i += SAM_THREADS) { sW[i] = w1x[i]; sW[256 + i] = w1r[i]; }
    for (int i = t; i < 64; i += SAM_THREADS)  { sW[192 + i] = b1x[i]; sW[448 + i] = b1r[i]; }
    {
        const float* wsrc[4] = {w2x, w2r, wax, war};
#pragma unroll
        for (int a = 0; a < 4; a++) {
            float* dst = sB + a * 2560;
            const float* s = wsrc[a];
            for (int i = t; i < 2048; i += SAM_THREADS) {
                int k = i >> 5, c = i & 31;
                dst[k * 40 + c] = __uint_as_float(f2tf32(s[i]));
            }
        }
    }
    __syncthreads();

    // ---- per-point inputs (2 threads per point) ----
    int p = t >> 1, half = t & 1;
    int cp = min(row0 + p, n - 1);
    if (half == 0) svx[p] = vidx[cp];
    float i0 = inp[(size_t)cp * 6 + 0], i1 = inp[(size_t)cp * 6 + 1], i2 = inp[(size_t)cp * 6 + 2];
    float i3 = inp[(size_t)cp * 6 + 3], i4 = inp[(size_t)cp * 6 + 4], i5 = inp[(size_t)cp * 6 + 5];

    // ---- layer1 xyz -> sA (each thread writes 32 of point p's 64 hiddens) ----
    {
        const float* W = sW; const float* B = sW + 192;
        int ob = half * 32;
#pragma unroll 8
        for (int o = 0; o < 32; o++) {
            int oo = ob + o;
            float a = B[oo] + i0 * W[oo] + i1 * W[64 + oo] + i2 * W[128 + oo];
            sA[p * 68 + oo] = tf32f(fmaxf(a, 0.f));
        }
    }
    __syncwarp();

    // ---- GEMM fx ----
    float fx[4][4];
#pragma unroll
    for (int nt = 0; nt < 4; nt++)
#pragma unroll
        for (int j = 0; j < 4; j++) fx[nt][j] = 0.f;
    gemm64x32(sA, sB, wr, g, t4, fx);
    __syncwarp();

    // bias+relu, write comb cols 0..31; meanwhile overwrite sA with th_r
#pragma unroll
    for (int nt = 0; nt < 4; nt++) {
        int c = nt * 8 + 2 * t4;
        float bc0 = __ldg(b2x + c), bc1 = __ldg(b2x + c + 1);
        fx[nt][0] = fmaxf(fx[nt][0] + bc0, 0.f);
        fx[nt][1] = fmaxf(fx[nt][1] + bc1, 0.f);
        fx[nt][2] = fmaxf(fx[nt][2] + bc0, 0.f);
        fx[nt][3] = fmaxf(fx[nt][3] + bc1, 0.f);
        int r = wr + g;
        *(float2*)(sC + r * 68 + c) = make_float2(tf32f(fx[nt][0]), tf32f(fx[nt][1]));
        *(float2*)(sC + (r + 8) * 68 + c) = make_float2(tf32f(fx[nt][2]), tf32f(fx[nt][3]));
    }
    {
        const float* W = sW + 256; const float* B = sW + 448;
        int ob = half * 32;
#pragma unroll 8
        for (int o = 0; o < 32; o++) {
            int oo = ob + o;
            float a = B[oo] + i3 * W[oo] + i4 * W[64 + oo] + i5 * W[128 + oo];
            sA[p * 68 + oo] = tf32f(fmaxf(a, 0.f));
        }
    }
    __syncwarp();

    // ---- GEMM fr ----
    float fr[4][4];
#pragma unroll
    for (int nt = 0; nt < 4; nt++)
#pragma unroll
        for (int j = 0; j < 4; j++) fr[nt][j] = 0.f;
    gemm64x32(sA, sB + 2560, wr, g, t4, fr);
#pragma unroll
    for (int nt = 0; nt < 4; nt++) {
        int c = nt * 8 + 2 * t4;
        float bc0 = __ldg(b2r + c), bc1 = __ldg(b2r + c + 1);
        fr[nt][0] = fmaxf(fr[nt][0] + bc0, 0.f);
        fr[nt][1] = fmaxf(fr[nt][1] + bc1, 0.f);
        fr[nt][2] = fmaxf(fr[nt][2] + bc0, 0.f);
        fr[nt][3] = fmaxf(fr[nt][3] + bc1, 0.f);
        int r = wr + g;
        *(float2*)(sC + r * 68 + 32 + c) = make_float2(tf32f(fr[nt][0]), tf32f(fr[nt][1]));
        *(float2*)(sC + (r + 8) * 68 + 32 + c) = make_float2(tf32f(fr[nt][2]), tf32f(fr[nt][3]));
    }
    __syncwarp();

    // ---- attention GEMMs ----
    float ax[4][4], ar[4][4];
#pragma unroll
    for (int nt = 0; nt < 4; nt++)
#pragma unroll
        for (int j = 0; j < 4; j++) { ax[nt][j] = 0.f; ar[nt][j] = 0.f; }
    gemm64x32(sC, sB + 2 * 2560, wr, g, t4, ax);
    gemm64x32(sC, sB + 3 * 2560, wr, g, t4, ar);

    // ---- epilogue: gates, pf2 store, atomicMax into g_vox ----
#pragma unroll
    for (int h2 = 0; h2 < 2; h2++) {
        int r = wr + g + 8 * h2;
        int pt = row0 + r;
        if (pt < n) {
            int vr = svx[r];
            float* pfr = g_pf2 + (size_t)pt * 128;
            float* vxr = g_vox + (size_t)vr * 128;
#pragma unroll
            for (int nt = 0; nt < 4; nt++) {
                int c = nt * 8 + 2 * t4;
                int j0 = 2 * h2, j1 = 2 * h2 + 1;
                float axa = ax[nt][j0] + __ldg(bax + c);
                float axb = ax[nt][j1] + __ldg(bax + c + 1);
                float ara = ar[nt][j0] + __ldg(bar + c);
                float arb = ar[nt][j1] + __ldg(bar + c + 1);
                float sxa = 1.f / (1.f + __expf(-axa));
                float sxb = 1.f / (1.f + __expf(-axb));
                float sra = 1.f / (1.f + __expf(-ara));
                float srb = 1.f / (1.f + __expf(-arb));
                float fxa = fx[nt][j0], fxb = fx[nt][j1];
                float fra = fr[nt][j0], frb = fr[nt][j1];
                float v1a = fxa * sxa, v1b = fxb * sxb;
                float v3a = fra * sra, v3b = frb * srb;
                *(float2*)(pfr + c)      = make_float2(fxa, fxb);
                *(float2*)(pfr + 32 + c) = make_float2(v1a, v1b);
                *(float2*)(pfr + 64 + c) = make_float2(fra, frb);
                *(float2*)(pfr + 96 + c) = make_float2(v3a, v3b);
                amax_pos(vxr + c, fxa);        amax_pos(vxr + c + 1, fxb);
                amax_pos(vxr + 32 + c, v1a);   amax_pos(vxr + 33 + c, v1b);
                amax_pos(vxr + 64 + c, fra);   amax_pos(vxr + 65 + c, frb);
                amax_pos(vxr + 96 + c, v3a);   amax_pos(vxr + 97 + c, v3b);
            }
        }
    }
}

// ---------------------------------------------------------------------------
// Generic tiled GEMM: out[M,NC] = relu(A[M,K] @ W[K,NC] + bias)
// ---------------------------------------------------------------------------
template <int K, int NC>
__global__ __launch_bounds__(256) void gemm_relu(
    const float* __restrict__ A, const float* __restrict__ W,
    const float* __restrict__ bias, float* __restrict__ out, int M)
{
    extern __shared__ float sm[];
    float* a_s = sm;
    float* b_s = sm + K * 68;
    const int TN = NC / 32;
    int t = threadIdx.x;
    int c = t & 31, r = t >> 5;
    int row0 = blockIdx.x * 64;
    {
        int row = t >> 2, q = t & 3;
        int gr = min(row0 + row, M - 1);
        const float4* src = (const float4*)(A + (size_t)gr * K + q * (K / 4));
#pragma unroll
        for (int u = 0; u < K / 16; ++u) {
            float4 v = src[u];
            int k = q * (K / 4) + 4 * u;
            a_s[(k + 0) * 68 + row] = v.x;
            a_s[(k + 1) * 68 + row] = v.y;
            a_s[(k + 2) * 68 + row] = v.z;
            a_s[(k + 3) * 68 + row] = v.w;
        }
    }
    float acc[8][TN];
#pragma unroll
    for (int i = 0; i < 8; i++)
#pragma unroll
        for (int j = 0; j < TN; j++) acc[i][j] = 0.f;
    for (int kc = 0; kc < K / 32; ++kc) {
        {
            const float4* ws = (const float4*)(W + (size_t)(kc * 32 + (t >> 3)) * NC + (t & 7) * (NC / 8));
            float4* wd = (float4*)(b_s + (t >> 3) * NC + (t & 7) * (NC / 8));
#pragma unroll
            for (int q = 0; q < NC / 32; q++) wd[q] = ws[q];
        }
        __syncthreads();
#pragma unroll
        for (int k = 0; k < 32; k++) {
            const float* ar = a_s + (kc * 32 + k) * 68 + 8 * r;
            float4 a0 = *(const float4*)ar;
            float4 a1 = *(const float4*)(ar + 4);
            float av[8] = {a0.x, a0.y, a0.z, a0.w, a1.x, a1.y, a1.z, a1.w};
            const float* br = b_s + k * NC + 4 * c;
            float bv[TN];
            {
                float4 b0 = *(const float4*)br;
                bv[0] = b0.x; bv[1] = b0.y; bv[2] = b0.z; bv[3] = b0.w;
            }
            if (TN == 8) {
                float4 b1v = *(const float4*)(br + NC / 2);
                bv[4] = b1v.x; bv[5] = b1v.y; bv[6] = b1v.z; bv[7] = b1v.w;
            }
#pragma unroll
            for (int i = 0; i < 8; i++)
#pragma unroll
                for (int j = 0; j < TN; j++) acc[i][j] += av[i] * bv[j];
        }
        __syncthreads();
    }
    float bb[TN];
#pragma unroll
    for (int j = 0; j < TN; j++) {
        int col = (j < 4) ? 4 * c + j : NC / 2 + 4 * c + (j - 4);
        bb[j] = bias[col];
    }
#pragma unroll
    for (int i = 0; i < 8; i++) {
        int row = row0 + 8 * r + i;
        if (row < M) {
#pragma unroll
            for (int j = 0; j < TN; j++) {
                int col = (j < 4) ? 4 * c + j : NC / 2 + 4 * c + (j - 4);
                out[(size_t)row * NC + col] = fmaxf(acc[i][j] + bb[j], 0.f);
            }
        }
    }
}

// ---------------------------------------------------------------------------
// Stage C via mma.sync tf32 (unchanged from R3)
// ---------------------------------------------------------------------------
#define SA_ST 260
#define SB_ST 264
#define SC_SMEM ((64 * SA_ST + 2 * 32 * SB_ST) * 4 + 256)

__global__ __launch_bounds__(256) void stage_c_mma(
    const int* __restrict__ vidx, int n,
    const float* __restrict__ b3, const float* __restrict__ b4)
{
    extern __shared__ float sm[];
    float* sA = sm;
    float* sB = sm + 64 * SA_ST;
    int* svx = (int*)(sB + 2 * 32 * SB_ST);

    int t = threadIdx.x;
    int lane = t & 31, wid = t >> 5;
    int g = lane >> 2, t4 = lane & 3;
    int wm = wid & 1, wn = wid >> 1;
    int row0 = blockIdx.x * 64;

    {
        int p = t >> 2, q = t & 3;
        int pt = row0 + p;
        int cp = min(pt, n - 1);
        int vr = vidx[cp];
        if (q == 0) svx[p] = vr;
        const float4* src = (q < 2)
            ? (const float4*)(g_voxf + (size_t)vr * 128 + q * 64)
            : (const float4*)(g_pf2 + (size_t)cp * 128 + (q - 2) * 64);
        float4* dst = (float4*)(sA + p * SA_ST + q * 64);
#pragma unroll
        for (int j = 0; j < 16; j++) {
            float4 v = src[j];
            v.x = __uint_as_float(f2tf32(v.x));
            v.y = __uint_as_float(f2tf32(v.y));
            v.z = __uint_as_float(f2tf32(v.z));
            v.w = __uint_as_float(f2tf32(v.w));
            dst[j] = v;
        }
    }

    float acc[2][8][4];
#pragma unroll
    for (int mt = 0; mt < 2; mt++)
#pragma unroll
        for (int nt = 0; nt < 8; nt++)
#pragma unroll
            for (int j = 0; j < 4; j++) acc[mt][nt][j] = 0.f;

    const float* wimg = (const float*)g_w3t;
    float4 pld[8];
    {
        const float4* ws = (const float4*)wimg;
#pragma unroll
        for (int i = 0; i < 8; i++) pld[i] = ws[t + i * 256];
#pragma unroll
        for (int i = 0; i < 8; i++) {
            int e = t + i * 256;
            int k = e >> 6, n4 = e & 63;
            *(float4*)(sB + k * SB_ST + n4 * 4) = pld[i];
        }
    }
    __syncthreads();

#pragma unroll 1
    for (int gg = 0; gg < 2; gg++) {
#pragma unroll 1
        for (int kc = 0; kc < 8; kc++) {
            if (kc < 7) {
                const float4* ws = (const float4*)(wimg + (kc + 1) * 32 * 256);
#pragma unroll
                for (int i = 0; i < 8; i++) pld[i] = ws[t + i * 256];
            }
            const float* bufB = sB + (kc & 1) * 32 * SB_ST;
#pragma unroll
            for (int k8 = 0; k8 < 4; k8++) {
                int k0 = kc * 32 + k8 * 8;
                uint32_t a[2][4];
#pragma unroll
                for (int mt = 0; mt < 2; mt++) {
                    const float* ap = sA + (wm * 32 + mt * 16 + g) * SA_ST + k0 + t4;
                    a[mt][0] = __float_as_uint(ap[0]);
                    a[mt][1] = __float_as_uint(ap[8 * SA_ST]);
                    a[mt][2] = __float_as_uint(ap[4]);
                    a[mt][3] = __float_as_uint(ap[8 * SA_ST + 4]);
                }
#pragma unroll
                for (int nt = 0; nt < 8; nt++) {
                    const float* bp = bufB + (k8 * 8 + t4) * SB_ST + wn * 64 + nt * 8 + g;
                    uint32_t b0 = __float_as_uint(bp[0]);
                    uint32_t b1 = __float_as_uint(bp[4 * SB_ST]);
#pragma unroll
                    for (int mt = 0; mt < 2; mt++) {
                        asm volatile(
                            "mma.sync.aligned.m16n8k8.row.col.f32.tf32.tf32.f32 "
                            "{%0,%1,%2,%3},{%4,%5,%6,%7},{%8,%9},{%0,%1,%2,%3};"
                            : "+f"(acc[mt][nt][0]), "+f"(acc[mt][nt][1]),
                              "+f"(acc[mt][nt][2]), "+f"(acc[mt][nt][3])
                            : "r"(a[mt][0]), "r"(a[mt][1]), "r"(a[mt][2]), "r"(a[mt][3]),
                              "r"(b0), "r"(b1));
                    }
                }
            }
            __syncthreads();
            if (kc < 7) {
                float* nb = sB + ((kc + 1) & 1) * 32 * SB_ST;
#pragma unroll
                for (int i = 0; i < 8; i++) {
                    int e = t + i * 256;
                    int k = e >> 6, n4 = e & 63;
                    *(float4*)(nb + k * SB_ST + n4 * 4) = pld[i];
                }
                __syncthreads();
            }
        }

        if (gg == 0) {
#pragma unroll
            for (int nt = 0; nt < 8; nt++) {
                int c = wn * 64 + nt * 8 + 2 * t4;
                float bc0 = __ldg(b3 + c), bc1 = __ldg(b3 + c + 1);
#pragma unroll
                for (int mt = 0; mt < 2; mt++) {
                    int r = wm * 32 + mt * 16 + g;
                    float h0 = fmaxf(acc[mt][nt][0] + bc0, 0.f);
                    float h1 = fmaxf(acc[mt][nt][1] + bc1, 0.f);
                    float h2 = fmaxf(acc[mt][nt][2] + bc0, 0.f);
                    float h3 = fmaxf(acc[mt][nt][3] + bc1, 0.f);
                    *(float2*)(sA + r * SA_ST + c) =
                        make_float2(__uint_as_float(f2tf32(h0)), __uint_as_float(f2tf32(h1)));
                    *(float2*)(sA + (r + 8) * SA_ST + c) =
                        make_float2(__uint_as_float(f2tf32(h2)), __uint_as_float(f2tf32(h3)));
                    acc[mt][nt][0] = 0.f; acc[mt][nt][1] = 0.f;
                    acc[mt][nt][2] = 0.f; acc[mt][nt][3] = 0.f;
                }
            }
            wimg = (const float*)g_w4t;
            {
                const float4* ws = (const float4*)wimg;
#pragma unroll
                for (int i = 0; i < 8; i++) pld[i] = ws[t + i * 256];
#pragma unroll
                for (int i = 0; i < 8; i++) {
                    int e = t + i * 256;
                    int k = e >> 6, n4 = e & 63;
                    *(float4*)(sB + k * SB_ST + n4 * 4) = pld[i];
                }
            }
            __syncthreads();
        }
    }

#pragma unroll
    for (int mt = 0; mt < 2; mt++) {
        int lr = wm * 32 + mt * 16 + g;
        int pt0 = row0 + lr, pt1 = pt0 + 8;
        int vr0 = svx[lr], vr1 = svx[lr + 8];
        bool ok0 = pt0 < n, ok1 = pt1 < n;
        float* d0 = g_vox2 + (size_t)vr0 * 256;
        float* d1 = g_vox2 + (size_t)vr1 * 256;
#pragma unroll
        for (int nt = 0; nt < 8; nt++) {
            int c = wn * 64 + nt * 8 + 2 * t4;
            float bc0 = __ldg(b4 + c), bc1 = __ldg(b4 + c + 1);
            if (ok0) {
                amax_pos(d0 + c,     acc[mt][nt][0] + bc0);
                amax_pos(d0 + c + 1, acc[mt][nt][1] + bc1);
            }
            if (ok1) {
                amax_pos(d1 + c,     acc[mt][nt][2] + bc0);
                amax_pos(d1 + c + 1, acc[mt][nt][3] + bc1);
            }
        }
    }
}

// ---------------------------------------------------------------------------
extern "C" void kernel_launch(void* const* d_in, const int* in_sizes, int n_in,
                              void* d_out, int out_size)
{
    const float* inp  = (const float*)d_in[0];
    const int*   vidx = (const int*)d_in[1];
    int base = (n_in >= 23) ? 3 : 2;
    const float* w1x = (const float*)d_in[base + 0];
    const float* b1x = (const float*)d_in[base + 1];
    const float* w2x = (const float*)d_in[base + 2];
    const float* b2x = (const float*)d_in[base + 3];
    const float* w1r = (const float*)d_in[base + 4];
    const float* b1r = (const float*)d_in[base + 5];
    const float* w2r = (const float*)d_in[base + 6];
    const float* b2r = (const float*)d_in[base + 7];
    const float* wax = (const float*)d_in[base + 8];
    const float* bax = (const float*)d_in[base + 9];
    const float* war = (const float*)d_in[base + 10];
    const float* bar = (const float*)d_in[base + 11];
    const float* wv1 = (const float*)d_in[base + 12];
    const float* bv1 = (const float*)d_in[base + 13];
    const float* w3  = (const float*)d_in[base + 14];
    const float* b3  = (const float*)d_in[base + 15];
    const float* w4  = (const float*)d_in[base + 16];
    const float* b4  = (const float*)d_in[base + 17];
    const float* wv2 = (const float*)d_in[base + 18];
    const float* bv2 = (const float*)d_in[base + 19];

    int n = in_sizes[0] / 6;
    int V = out_size / 256;

    const int G1_SMEM = (128 * 68 + 32 * 128) * 4;
    const int G2_SMEM = (256 * 68 + 32 * 256) * 4;

    cudaFuncSetAttribute(stage_a_mma, cudaFuncAttributeMaxDynamicSharedMemorySize, SAM_SMEM);
    cudaFuncSetAttribute(stage_c_mma, cudaFuncAttributeMaxDynamicSharedMemorySize, SC_SMEM);
    cudaFuncSetAttribute(gemm_relu<128, 128>, cudaFuncAttributeMaxDynamicSharedMemorySize, G1_SMEM);
    cudaFuncSetAttribute(gemm_relu<256, 256>, cudaFuncAttributeMaxDynamicSharedMemorySize, G2_SMEM);

    float *p_vox, *p_voxf, *p_vox2, *p_w3t, *p_w4t;
    cudaGetSymbolAddress((void**)&p_vox, g_vox);
    cudaGetSymbolAddress((void**)&p_voxf, g_voxf);
    cudaGetSymbolAddress((void**)&p_vox2, g_vox2);
    cudaGetSymbolAddress((void**)&p_w3t, g_w3t);
    cudaGetSymbolAddress((void**)&p_w4t, g_w4t);

    int zb = (V * 256 + 255) / 256;
    zero_k<<<zb, 256>>>(V * 128, V * 256);
    prep_tf32<<<256, 256>>>(w3, p_w3t);
    prep_tf32<<<256, 256>>>(w4, p_w4t);

    stage_a_mma<<<(n + 127) / 128, SAM_THREADS, SAM_SMEM>>>(
        inp, vidx, n, w1x, b1x, w2x, b2x, w1r, b1r, w2r, b2r, wax, bax, war, bar);

    gemm_relu<128, 128><<<(V + 63) / 64, 256, G1_SMEM>>>(p_vox, wv1, bv1, p_voxf, V);

    stage_c_mma<<<(n + 63) / 64, 256, SC_SMEM>>>(vidx, n, b3, b4);

    gemm_relu<256, 256><<<(V + 63) / 64, 256, G2_SMEM>>>(p_vox2, wv2, bv2, (float*)d_out, V);
}

// round 5
// speedup vs baseline: 3.7144x; 1.1717x over previous
#include <cuda_runtime.h>
#include <cstdint>
#include <math.h>

#define MAXN 500000
#define MAXV 50000

// ---- scratch (static __device__ arrays; allocation-free) ----
__device__ __align__(128) float g_pf2[(size_t)MAXN * 128];
__device__ __align__(128) float g_vox[(size_t)MAXV * 128];
__device__ __align__(128) float g_voxf[(size_t)MAXV * 128];
__device__ __align__(128) float g_vox2[(size_t)MAXV * 256];
__device__ __align__(128) float g_w3t[65536];   // w3 tf32
__device__ __align__(128) float g_w4t[65536];   // w4 tf32
__device__ __align__(128) float g_wvt[65536];   // wv2 tf32

__device__ __forceinline__ void amax_pos(float* addr, float v) {
    if (v > 0.f) atomicMax((int*)addr, __float_as_int(v));
}

__device__ __forceinline__ uint32_t f2tf32(float f) {
    uint32_t r;
    asm("cvt.rna.tf32.f32 %0, %1;" : "=r"(r) : "f"(f));
    return r;
}
__device__ __forceinline__ float tf32f(float f) { return __uint_as_float(f2tf32(f)); }

// ---------------------------------------------------------------------------
__global__ void zero_k(int na, int nb) {
    int i = blockIdx.x * blockDim.x + threadIdx.x;
    int stride = gridDim.x * blockDim.x;
    for (int j = i; j < nb; j += stride) {
        if (j < na) g_vox[j] = 0.f;
        g_vox2[j] = 0.f;
    }
}

__global__ void prep_tf32(const float* __restrict__ w, float* __restrict__ dst) {
    int i = blockIdx.x * blockDim.x + threadIdx.x;
    if (i < 65536) dst[i] = __uint_as_float(f2tf32(w[i]));
}

// ---------------------------------------------------------------------------
// warp micro-GEMM helper: [16x64]@[64x32], A stride 68, B stride 40
// ---------------------------------------------------------------------------
__device__ __forceinline__ void gemm64x32(const float* __restrict__ As,
                                          const float* __restrict__ Bt,
                                          int wr, int g, int t4, float acc[4][4]) {
#pragma unroll
    for (int k8 = 0; k8 < 8; k8++) {
        const float* ap = As + (wr + g) * 68 + k8 * 8 + t4;
        uint32_t a0 = __float_as_uint(ap[0]);
        uint32_t a1 = __float_as_uint(ap[8 * 68]);
        uint32_t a2 = __float_as_uint(ap[4]);
        uint32_t a3 = __float_as_uint(ap[8 * 68 + 4]);
#pragma unroll
        for (int nt = 0; nt < 4; nt++) {
            const float* bp = Bt + (k8 * 8 + t4) * 40 + nt * 8 + g;
            uint32_t b0 = __float_as_uint(bp[0]);
            uint32_t b1 = __float_as_uint(bp[4 * 40]);
            asm volatile(
                "mma.sync.aligned.m16n8k8.row.col.f32.tf32.tf32.f32 "
                "{%0,%1,%2,%3},{%4,%5,%6,%7},{%8,%9},{%0,%1,%2,%3};"
                : "+f"(acc[nt][0]), "+f"(acc[nt][1]), "+f"(acc[nt][2]), "+f"(acc[nt][3])
                : "r"(a0), "r"(a1), "r"(a2), "r"(a3), "r"(b0), "r"(b1));
        }
    }
}

// ---------------------------------------------------------------------------
// Stage A via mma.sync tf32 (unchanged from R4)
// ---------------------------------------------------------------------------
#define SAM_THREADS 256
#define SAM_SMEM (28288 * 4)

__global__ __launch_bounds__(SAM_THREADS) void stage_a_mma(
    const float* __restrict__ inp, const int* __restrict__ vidx, int n,
    const float* __restrict__ w1x, const float* __restrict__ b1x,
    const float* __restrict__ w2x, const float* __restrict__ b2x,
    const float* __restrict__ w1r, const float* __restrict__ b1r,
    const float* __restrict__ w2r, const float* __restrict__ b2r,
    const float* __restrict__ wax, const float* __restrict__ bax,
    const float* __restrict__ war, const float* __restrict__ bar)
{
    extern __shared__ float sm[];
    float* sW = sm;
    float* sB = sm + 512;
    float* sA = sm + 10752;
    float* sC = sm + 19456;
    int*   svx = (int*)(sm + 28160);

    int t = threadIdx.x;
    int lane = t & 31, w = t >> 5;
    int g = lane >> 2, t4 = lane & 3;
    int wr = 16 * w;
    int row0 = blockIdx.x * 128;

    for (int i = t; i < 192; i += SAM_THREADS) { sW[i] = w1x[i]; sW[256 + i] = w1r[i]; }
    for (int i = t; i < 64; i += SAM_THREADS)  { sW[192 + i] = b1x[i]; sW[448 + i] = b1r[i]; }
    {
        const float* wsrc[4] = {w2x, w2r, wax, war};
#pragma unroll
        for (int a = 0; a < 4; a++) {
            float* dst = sB + a * 2560;
            const float* s = wsrc[a];
            for (int i = t; i < 2048; i += SAM_THREADS) {
                int k = i >> 5, c = i & 31;
                dst[k * 40 + c] = __uint_as_float(f2tf32(s[i]));
            }
        }
    }
    __syncthreads();

    int p = t >> 1, half = t & 1;
    int cp = min(row0 + p, n - 1);
    if (half == 0) svx[p] = vidx[cp];
    float i0 = inp[(size_t)cp * 6 + 0], i1 = inp[(size_t)cp * 6 + 1], i2 = inp[(size_t)cp * 6 + 2];
    float i3 = inp[(size_t)cp * 6 + 3], i4 = inp[(size_t)cp * 6 + 4], i5 = inp[(size_t)cp * 6 + 5];

    {
        const float* W = sW; const float* B = sW + 192;
        int ob = half * 32;
#pragma unroll 8
        for (int o = 0; o < 32; o++) {
            int oo = ob + o;
            float a = B[oo] + i0 * W[oo] + i1 * W[64 + oo] + i2 * W[128 + oo];
            sA[p * 68 + oo] = tf32f(fmaxf(a, 0.f));
        }
    }
    __syncwarp();

    float fx[4][4];
#pragma unroll
    for (int nt = 0; nt < 4; nt++)
#pragma unroll
        for (int j = 0; j < 4; j++) fx[nt][j] = 0.f;
    gemm64x32(sA, sB, wr, g, t4, fx);
    __syncwarp();

#pragma unroll
    for (int nt = 0; nt < 4; nt++) {
        int c = nt * 8 + 2 * t4;
        float bc0 = __ldg(b2x + c), bc1 = __ldg(b2x + c + 1);
        fx[nt][0] = fmaxf(fx[nt][0] + bc0, 0.f);
        fx[nt][1] = fmaxf(fx[nt][1] + bc1, 0.f);
        fx[nt][2] = fmaxf(fx[nt][2] + bc0, 0.f);
        fx[nt][3] = fmaxf(fx[nt][3] + bc1, 0.f);
        int r = wr + g;
        *(float2*)(sC + r * 68 + c) = make_float2(tf32f(fx[nt][0]), tf32f(fx[nt][1]));
        *(float2*)(sC + (r + 8) * 68 + c) = make_float2(tf32f(fx[nt][2]), tf32f(fx[nt][3]));
    }
    {
        const float* W = sW + 256; const float* B = sW + 448;
        int ob = half * 32;
#pragma unroll 8
        for (int o = 0; o < 32; o++) {
            int oo = ob + o;
            float a = B[oo] + i3 * W[oo] + i4 * W[64 + oo] + i5 * W[128 + oo];
            sA[p * 68 + oo] = tf32f(fmaxf(a, 0.f));
        }
    }
    __syncwarp();

    float fr[4][4];
#pragma unroll
    for (int nt = 0; nt < 4; nt++)
#pragma unroll
        for (int j = 0; j < 4; j++) fr[nt][j] = 0.f;
    gemm64x32(sA, sB + 2560, wr, g, t4, fr);
#pragma unroll
    for (int nt = 0; nt < 4; nt++) {
        int c = nt * 8 + 2 * t4;
        float bc0 = __ldg(b2r + c), bc1 = __ldg(b2r + c + 1);
        fr[nt][0] = fmaxf(fr[nt][0] + bc0, 0.f);
        fr[nt][1] = fmaxf(fr[nt][1] + bc1, 0.f);
        fr[nt][2] = fmaxf(fr[nt][2] + bc0, 0.f);
        fr[nt][3] = fmaxf(fr[nt][3] + bc1, 0.f);
        int r = wr + g;
        *(float2*)(sC + r * 68 + 32 + c) = make_float2(tf32f(fr[nt][0]), tf32f(fr[nt][1]));
        *(float2*)(sC + (r + 8) * 68 + 32 + c) = make_float2(tf32f(fr[nt][2]), tf32f(fr[nt][3]));
    }
    __syncwarp();

    float ax[4][4], ar[4][4];
#pragma unroll
    for (int nt = 0; nt < 4; nt++)
#pragma unroll
        for (int j = 0; j < 4; j++) { ax[nt][j] = 0.f; ar[nt][j] = 0.f; }
    gemm64x32(sC, sB + 2 * 2560, wr, g, t4, ax);
    gemm64x32(sC, sB + 3 * 2560, wr, g, t4, ar);

#pragma unroll
    for (int h2 = 0; h2 < 2; h2++) {
        int r = wr + g + 8 * h2;
        int pt = row0 + r;
        if (pt < n) {
            int vr = svx[r];
            float* pfr = g_pf2 + (size_t)pt * 128;
            float* vxr = g_vox + (size_t)vr * 128;
#pragma unroll
            for (int nt = 0; nt < 4; nt++) {
                int c = nt * 8 + 2 * t4;
                int j0 = 2 * h2, j1 = 2 * h2 + 1;
                float axa = ax[nt][j0] + __ldg(bax + c);
                float axb = ax[nt][j1] + __ldg(bax + c + 1);
                float ara = ar[nt][j0] + __ldg(bar + c);
                float arb = ar[nt][j1] + __ldg(bar + c + 1);
                float sxa = 1.f / (1.f + __expf(-axa));
                float sxb = 1.f / (1.f + __expf(-axb));
                float sra = 1.f / (1.f + __expf(-ara));
                float srb = 1.f / (1.f + __expf(-arb));
                float fxa = fx[nt][j0], fxb = fx[nt][j1];
                float fra = fr[nt][j0], frb = fr[nt][j1];
                float v1a = fxa * sxa, v1b = fxb * sxb;
                float v3a = fra * sra, v3b = frb * srb;
                *(float2*)(pfr + c)      = make_float2(fxa, fxb);
                *(float2*)(pfr + 32 + c) = make_float2(v1a, v1b);
                *(float2*)(pfr + 64 + c) = make_float2(fra, frb);
                *(float2*)(pfr + 96 + c) = make_float2(v3a, v3b);
                amax_pos(vxr + c, fxa);        amax_pos(vxr + c + 1, fxb);
                amax_pos(vxr + 32 + c, v1a);   amax_pos(vxr + 33 + c, v1b);
                amax_pos(vxr + 64 + c, fra);   amax_pos(vxr + 65 + c, frb);
                amax_pos(vxr + 96 + c, v3a);   amax_pos(vxr + 97 + c, v3b);
            }
        }
    }
}

// ---------------------------------------------------------------------------
// Generic tiled fp32 GEMM (kept for the small wv1 layer)
// ---------------------------------------------------------------------------
template <int K, int NC>
__global__ __launch_bounds__(256) void gemm_relu(
    const float* __restrict__ A, const float* __restrict__ W,
    const float* __restrict__ bias, float* __restrict__ out, int M)
{
    extern __shared__ float sm[];
    float* a_s = sm;
    float* b_s = sm + K * 68;
    const int TN = NC / 32;
    int t = threadIdx.x;
    int c = t & 31, r = t >> 5;
    int row0 = blockIdx.x * 64;
    {
        int row = t >> 2, q = t & 3;
        int gr = min(row0 + row, M - 1);
        const float4* src = (const float4*)(A + (size_t)gr * K + q * (K / 4));
#pragma unroll
        for (int u = 0; u < K / 16; ++u) {
            float4 v = src[u];
            int k = q * (K / 4) + 4 * u;
            a_s[(k + 0) * 68 + row] = v.x;
            a_s[(k + 1) * 68 + row] = v.y;
            a_s[(k + 2) * 68 + row] = v.z;
            a_s[(k + 3) * 68 + row] = v.w;
        }
    }
    float acc[8][TN];
#pragma unroll
    for (int i = 0; i < 8; i++)
#pragma unroll
        for (int j = 0; j < TN; j++) acc[i][j] = 0.f;
    for (int kc = 0; kc < K / 32; ++kc) {
        {
            const float4* ws = (const float4*)(W + (size_t)(kc * 32 + (t >> 3)) * NC + (t & 7) * (NC / 8));
            float4* wd = (float4*)(b_s + (t >> 3) * NC + (t & 7) * (NC / 8));
#pragma unroll
            for (int q = 0; q < NC / 32; q++) wd[q] = ws[q];
        }
        __syncthreads();
#pragma unroll
        for (int k = 0; k < 32; k++) {
            const float* ar = a_s + (kc * 32 + k) * 68 + 8 * r;
            float4 a0 = *(const float4*)ar;
            float4 a1 = *(const float4*)(ar + 4);
            float av[8] = {a0.x, a0.y, a0.z, a0.w, a1.x, a1.y, a1.z, a1.w};
            const float* br = b_s + k * NC + 4 * c;
            float bv[TN];
            {
                float4 b0 = *(const float4*)br;
                bv[0] = b0.x; bv[1] = b0.y; bv[2] = b0.z; bv[3] = b0.w;
            }
            if (TN == 8) {
                float4 b1v = *(const float4*)(br + NC / 2);
                bv[4] = b1v.x; bv[5] = b1v.y; bv[6] = b1v.z; bv[7] = b1v.w;
            }
#pragma unroll
            for (int i = 0; i < 8; i++)
#pragma unroll
                for (int j = 0; j < TN; j++) acc[i][j] += av[i] * bv[j];
        }
        __syncthreads();
    }
    float bb[TN];
#pragma unroll
    for (int j = 0; j < TN; j++) {
        int col = (j < 4) ? 4 * c + j : NC / 2 + 4 * c + (j - 4);
        bb[j] = bias[col];
    }
#pragma unroll
    for (int i = 0; i < 8; i++) {
        int row = row0 + 8 * r + i;
        if (row < M) {
#pragma unroll
            for (int j = 0; j < TN; j++) {
                int col = (j < 4) ? 4 * c + j : NC / 2 + 4 * c + (j - 4);
                out[(size_t)row * NC + col] = fmaxf(acc[i][j] + bb[j], 0.f);
            }
        }
    }
}

// ---------------------------------------------------------------------------
// Stage C v2: 128-point tiles, 512 threads (16 warps, 4m x 4n), two chained
// GEMMs [128x256]@[256x256] via m16n8k8 tf32, epilogue2 atomicMax scatter.
// ---------------------------------------------------------------------------
#define SA_ST 260
#define SB_ST 264
#define SC_SMEM ((128 * SA_ST + 2 * 32 * SB_ST + 128) * 4)

__global__ __launch_bounds__(512) void stage_c_mma(
    const int* __restrict__ vidx, int n,
    const float* __restrict__ b3, const float* __restrict__ b4)
{
    extern __shared__ float sm[];
    float* sA = sm;                          // [128][SA_ST]
    float* sB = sm + 128 * SA_ST;            // [2][32][SB_ST]
    int* svx = (int*)(sB + 2 * 32 * SB_ST);  // [128]

    int t = threadIdx.x;
    int lane = t & 31, wid = t >> 5;
    int g = lane >> 2, t4 = lane & 3;
    int wm = wid & 3, wn = wid >> 2;
    int row0 = blockIdx.x * 128;

    // ---- gather pf3 = [voxf[vidx[p]], pf2[p]] into sA as tf32 ----
    {
        int p = t >> 2, q = t & 3;
        int pt = row0 + p;
        int cp = min(pt, n - 1);
        int vr = vidx[cp];
        if (q == 0) svx[p] = vr;
        const float4* src = (q < 2)
            ? (const float4*)(g_voxf + (size_t)vr * 128 + q * 64)
            : (const float4*)(g_pf2 + (size_t)cp * 128 + (q - 2) * 64);
        float4* dst = (float4*)(sA + p * SA_ST + q * 64);
#pragma unroll
        for (int j = 0; j < 16; j++) {
            float4 v = src[j];
            v.x = __uint_as_float(f2tf32(v.x));
            v.y = __uint_as_float(f2tf32(v.y));
            v.z = __uint_as_float(f2tf32(v.z));
            v.w = __uint_as_float(f2tf32(v.w));
            dst[j] = v;
        }
    }

    float acc[2][8][4];
#pragma unroll
    for (int mt = 0; mt < 2; mt++)
#pragma unroll
        for (int nt = 0; nt < 8; nt++)
#pragma unroll
            for (int j = 0; j < 4; j++) acc[mt][nt][j] = 0.f;

    const float* wimg = (const float*)g_w3t;
    float4 pld[4];
    {
        const float4* ws = (const float4*)wimg;
#pragma unroll
        for (int i = 0; i < 4; i++) pld[i] = ws[t + i * 512];
#pragma unroll
        for (int i = 0; i < 4; i++) {
            int e = t + i * 512;
            int k = e >> 6, n4 = e & 63;
            *(float4*)(sB + k * SB_ST + n4 * 4) = pld[i];
        }
    }
    __syncthreads();

#pragma unroll 1
    for (int gg = 0; gg < 2; gg++) {
#pragma unroll 1
        for (int kc = 0; kc < 8; kc++) {
            if (kc < 7) {
                const float4* ws = (const float4*)(wimg + (kc + 1) * 32 * 256);
#pragma unroll
                for (int i = 0; i < 4; i++) pld[i] = ws[t + i * 512];
            }
            const float* bufB = sB + (kc & 1) * 32 * SB_ST;
#pragma unroll
            for (int k8 = 0; k8 < 4; k8++) {
                int k0 = kc * 32 + k8 * 8;
                uint32_t a[2][4];
#pragma unroll
                for (int mt = 0; mt < 2; mt++) {
                    const float* ap = sA + (wm * 32 + mt * 16 + g) * SA_ST + k0 + t4;
                    a[mt][0] = __float_as_uint(ap[0]);
                    a[mt][1] = __float_as_uint(ap[8 * SA_ST]);
                    a[mt][2] = __float_as_uint(ap[4]);
                    a[mt][3] = __float_as_uint(ap[8 * SA_ST + 4]);
                }
#pragma unroll
                for (int nt = 0; nt < 8; nt++) {
                    const float* bp = bufB + (k8 * 8 + t4) * SB_ST + wn * 64 + nt * 8 + g;
                    uint32_t b0 = __float_as_uint(bp[0]);
                    uint32_t b1 = __float_as_uint(bp[4 * SB_ST]);
#pragma unroll
                    for (int mt = 0; mt < 2; mt++) {
                        asm volatile(
                            "mma.sync.aligned.m16n8k8.row.col.f32.tf32.tf32.f32 "
                            "{%0,%1,%2,%3},{%4,%5,%6,%7},{%8,%9},{%0,%1,%2,%3};"
                            : "+f"(acc[mt][nt][0]), "+f"(acc[mt][nt][1]),
                              "+f"(acc[mt][nt][2]), "+f"(acc[mt][nt][3])
                            : "r"(a[mt][0]), "r"(a[mt][1]), "r"(a[mt][2]), "r"(a[mt][3]),
                              "r"(b0), "r"(b1));
                    }
                }
            }
            __syncthreads();
            if (kc < 7) {
                float* nb = sB + ((kc + 1) & 1) * 32 * SB_ST;
#pragma unroll
                for (int i = 0; i < 4; i++) {
                    int e = t + i * 512;
                    int k = e >> 6, n4 = e & 63;
                    *(float4*)(nb + k * SB_ST + n4 * 4) = pld[i];
                }
                __syncthreads();
            }
        }

        if (gg == 0) {
            // epilogue1: h = relu(acc + b3) -> sA (tf32), reset acc
#pragma unroll
            for (int nt = 0; nt < 8; nt++) {
                int c = wn * 64 + nt * 8 + 2 * t4;
                float bc0 = __ldg(b3 + c), bc1 = __ldg(b3 + c + 1);
#pragma unroll
                for (int mt = 0; mt < 2; mt++) {
                    int r = wm * 32 + mt * 16 + g;
                    float h0 = fmaxf(acc[mt][nt][0] + bc0, 0.f);
                    float h1 = fmaxf(acc[mt][nt][1] + bc1, 0.f);
                    float h2 = fmaxf(acc[mt][nt][2] + bc0, 0.f);
                    float h3 = fmaxf(acc[mt][nt][3] + bc1, 0.f);
                    *(float2*)(sA + r * SA_ST + c) =
                        make_float2(tf32f(h0), tf32f(h1));
                    *(float2*)(sA + (r + 8) * SA_ST + c) =
                        make_float2(tf32f(h2), tf32f(h3));
                    acc[mt][nt][0] = 0.f; acc[mt][nt][1] = 0.f;
                    acc[mt][nt][2] = 0.f; acc[mt][nt][3] = 0.f;
                }
            }
            wimg = (const float*)g_w4t;
            {
                const float4* ws = (const float4*)wimg;
#pragma unroll
                for (int i = 0; i < 4; i++) pld[i] = ws[t + i * 512];
#pragma unroll
                for (int i = 0; i < 4; i++) {
                    int e = t + i * 512;
                    int k = e >> 6, n4 = e & 63;
                    *(float4*)(sB + k * SB_ST + n4 * 4) = pld[i];
                }
            }
            __syncthreads();
        }
    }

    // epilogue2: pf5 = relu(acc + b4) -> atomicMax scatter into g_vox2
#pragma unroll
    for (int mt = 0; mt < 2; mt++) {
        int lr = wm * 32 + mt * 16 + g;
        int pt0 = row0 + lr, pt1 = pt0 + 8;
        int vr0 = svx[lr], vr1 = svx[lr + 8];
        bool ok0 = pt0 < n, ok1 = pt1 < n;
        float* d0 = g_vox2 + (size_t)vr0 * 256;
        float* d1 = g_vox2 + (size_t)vr1 * 256;
#pragma unroll
        for (int nt = 0; nt < 8; nt++) {
            int c = wn * 64 + nt * 8 + 2 * t4;
            float bc0 = __ldg(b4 + c), bc1 = __ldg(b4 + c + 1);
            if (ok0) {
                amax_pos(d0 + c,     acc[mt][nt][0] + bc0);
                amax_pos(d0 + c + 1, acc[mt][nt][1] + bc1);
            }
            if (ok1) {
                amax_pos(d1 + c,     acc[mt][nt][2] + bc0);
                amax_pos(d1 + c + 1, acc[mt][nt][3] + bc1);
            }
        }
    }
}

// ---------------------------------------------------------------------------
// Output GEMM via mma: out[M,256] = relu(A[M,256] @ Wt + bias), direct store.
// Same tiling as stage_c (128 rows, 512 threads), single GEMM.
// ---------------------------------------------------------------------------
__global__ __launch_bounds__(512) void gemm_out_mma(
    const float* __restrict__ A, const float* __restrict__ bias,
    float* __restrict__ out, int M)
{
    extern __shared__ float sm[];
    float* sA = sm;
    float* sB = sm + 128 * SA_ST;

    int t = threadIdx.x;
    int lane = t & 31, wid = t >> 5;
    int g = lane >> 2, t4 = lane & 3;
    int wm = wid & 3, wn = wid >> 2;
    int row0 = blockIdx.x * 128;

    {
        int p = t >> 2, q = t & 3;
        int cp = min(row0 + p, M - 1);
        const float4* src = (const float4*)(A + (size_t)cp * 256 + q * 64);
        float4* dst = (float4*)(sA + p * SA_ST + q * 64);
#pragma unroll
        for (int j = 0; j < 16; j++) {
            float4 v = src[j];
            v.x = tf32f(v.x); v.y = tf32f(v.y);
            v.z = tf32f(v.z); v.w = tf32f(v.w);
            dst[j] = v;
        }
    }

    float acc[2][8][4];
#pragma unroll
    for (int mt = 0; mt < 2; mt++)
#pragma unroll
        for (int nt = 0; nt < 8; nt++)
#pragma unroll
            for (int j = 0; j < 4; j++) acc[mt][nt][j] = 0.f;

    const float* wimg = (const float*)g_wvt;
    float4 pld[4];
    {
        const float4* ws = (const float4*)wimg;
#pragma unroll
        for (int i = 0; i < 4; i++) pld[i] = ws[t + i * 512];
#pragma unroll
        for (int i = 0; i < 4; i++) {
            int e = t + i * 512;
            int k = e >> 6, n4 = e & 63;
            *(float4*)(sB + k * SB_ST + n4 * 4) = pld[i];
        }
    }
    __syncthreads();

#pragma unroll 1
    for (int kc = 0; kc < 8; kc++) {
        if (kc < 7) {
            const float4* ws = (const float4*)(wimg + (kc + 1) * 32 * 256);
#pragma unroll
            for (int i = 0; i < 4; i++) pld[i] = ws[t + i * 512];
        }
        const float* bufB = sB + (kc & 1) * 32 * SB_ST;
#pragma unroll
        for (int k8 = 0; k8 < 4; k8++) {
            int k0 = kc * 32 + k8 * 8;
            uint32_t a[2][4];
#pragma unroll
            for (int mt = 0; mt < 2; mt++) {
                const float* ap = sA + (wm * 32 + mt * 16 + g) * SA_ST + k0 + t4;
                a[mt][0] = __float_as_uint(ap[0]);
                a[mt][1] = __float_as_uint(ap[8 * SA_ST]);
                a[mt][2] = __float_as_uint(ap[4]);
                a[mt][3] = __float_as_uint(ap[8 * SA_ST + 4]);
            }
#pragma unroll
            for (int nt = 0; nt < 8; nt++) {
                const float* bp = bufB + (k8 * 8 + t4) * SB_ST + wn * 64 + nt * 8 + g;
                uint32_t b0 = __float_as_uint(bp[0]);
                uint32_t b1 = __float_as_uint(bp[4 * SB_ST]);
#pragma unroll
                for (int mt = 0; mt < 2; mt++) {
                    asm volatile(
                        "mma.sync.aligned.m16n8k8.row.col.f32.tf32.tf32.f32 "
                        "{%0,%1,%2,%3},{%4,%5,%6,%7},{%8,%9},{%0,%1,%2,%3};"
                        : "+f"(acc[mt][nt][0]), "+f"(acc[mt][nt][1]),
                          "+f"(acc[mt][nt][2]), "+f"(acc[mt][nt][3])
                        : "r"(a[mt][0]), "r"(a[mt][1]), "r"(a[mt][2]), "r"(a[mt][3]),
                          "r"(b0), "r"(b1));
                }
            }
        }
        __syncthreads();
        if (kc < 7) {
            float* nb = sB + ((kc + 1) & 1) * 32 * SB_ST;
#pragma unroll
            for (int i = 0; i < 4; i++) {
                int e = t + i * 512;
                int k = e >> 6, n4 = e & 63;
                *(float4*)(nb + k * SB_ST + n4 * 4) = pld[i];
            }
            __syncthreads();
        }
    }

#pragma unroll
    for (int mt = 0; mt < 2; mt++) {
        int lr = wm * 32 + mt * 16 + g;
        int r0 = row0 + lr, r1 = r0 + 8;
#pragma unroll
        for (int nt = 0; nt < 8; nt++) {
            int c = wn * 64 + nt * 8 + 2 * t4;
            float bc0 = __ldg(bias + c), bc1 = __ldg(bias + c + 1);
            if (r0 < M)
                *(float2*)(out + (size_t)r0 * 256 + c) =
                    make_float2(fmaxf(acc[mt][nt][0] + bc0, 0.f), fmaxf(acc[mt][nt][1] + bc1, 0.f));
            if (r1 < M)
                *(float2*)(out + (size_t)r1 * 256 + c) =
                    make_float2(fmaxf(acc[mt][nt][2] + bc0, 0.f), fmaxf(acc[mt][nt][3] + bc1, 0.f));
        }
    }
}

// ---------------------------------------------------------------------------
extern "C" void kernel_launch(void* const* d_in, const int* in_sizes, int n_in,
                              void* d_out, int out_size)
{
    const float* inp  = (const float*)d_in[0];
    const int*   vidx = (const int*)d_in[1];
    int base = (n_in >= 23) ? 3 : 2;
    const float* w1x = (const float*)d_in[base + 0];
    const float* b1x = (const float*)d_in[base + 1];
    const float* w2x = (const float*)d_in[base + 2];
    const float* b2x = (const float*)d_in[base + 3];
    const float* w1r = (const float*)d_in[base + 4];
    const float* b1r = (const float*)d_in[base + 5];
    const float* w2r = (const float*)d_in[base + 6];
    const float* b2r = (const float*)d_in[base + 7];
    const float* wax = (const float*)d_in[base + 8];
    const float* bax = (const float*)d_in[base + 9];
    const float* war = (const float*)d_in[base + 10];
    const float* bar = (const float*)d_in[base + 11];
    const float* wv1 = (const float*)d_in[base + 12];
    const float* bv1 = (const float*)d_in[base + 13];
    const float* w3  = (const float*)d_in[base + 14];
    const float* b3  = (const float*)d_in[base + 15];
    const float* w4  = (const float*)d_in[base + 16];
    const float* b4  = (const float*)d_in[base + 17];
    const float* wv2 = (const float*)d_in[base + 18];
    const float* bv2 = (const float*)d_in[base + 19];

    int n = in_sizes[0] / 6;
    int V = out_size / 256;

    const int G1_SMEM = (128 * 68 + 32 * 128) * 4;

    cudaFuncSetAttribute(stage_a_mma, cudaFuncAttributeMaxDynamicSharedMemorySize, SAM_SMEM);
    cudaFuncSetAttribute(stage_c_mma, cudaFuncAttributeMaxDynamicSharedMemorySize, SC_SMEM);
    cudaFuncSetAttribute(gemm_out_mma, cudaFuncAttributeMaxDynamicSharedMemorySize, SC_SMEM);
    cudaFuncSetAttribute(gemm_relu<128, 128>, cudaFuncAttributeMaxDynamicSharedMemorySize, G1_SMEM);

    float *p_vox, *p_voxf, *p_vox2, *p_w3t, *p_w4t, *p_wvt;
    cudaGetSymbolAddress((void**)&p_vox, g_vox);
    cudaGetSymbolAddress((void**)&p_voxf, g_voxf);
    cudaGetSymbolAddress((void**)&p_vox2, g_vox2);
    cudaGetSymbolAddress((void**)&p_w3t, g_w3t);
    cudaGetSymbolAddress((void**)&p_w4t, g_w4t);
    cudaGetSymbolAddress((void**)&p_wvt, g_wvt);

    int zb = (V * 256 + 255) / 256;
    zero_k<<<zb, 256>>>(V * 128, V * 256);
    prep_tf32<<<256, 256>>>(w3, p_w3t);
    prep_tf32<<<256, 256>>>(w4, p_w4t);
    prep_tf32<<<256, 256>>>(wv2, p_wvt);

    stage_a_mma<<<(n + 127) / 128, SAM_THREADS, SAM_SMEM>>>(
        inp, vidx, n, w1x, b1x, w2x, b2x, w1r, b1r, w2r, b2r, wax, bax, war, bar);

    gemm_relu<128, 128><<<(V + 63) / 64, 256, G1_SMEM>>>(p_vox, wv1, bv1, p_voxf, V);

    stage_c_mma<<<(n + 127) / 128, 512, SC_SMEM>>>(vidx, n, b3, b4);

    gemm_out_mma<<<(V + 127) / 128, 512, SC_SMEM>>>(p_vox2, bv2, (float*)d_out, V);
}